// round 8
// baseline (speedup 1.0000x reference)
#include <cuda_runtime.h>

#define D          1024
#define NHEAD      10004
#define SHORTLIST  10000
#define NPROJ      960
#define NCL        90000
#define NTGT       4096

#define FK_THREADS 512
#define FK_WARPS   16
#define PROJ_BLOCKS 60                                     // 960 rows / 16 warps
#define HEAD_BLOCKS ((NHEAD + FK_WARPS - 1) / FK_WARPS)    // 626
#define CL_CHUNKS   32500    // 10000 + 10000 + 10000 + 2500 (2KB chunks)
#define CL_BLOCKS   ((CL_CHUNKS + FK_WARPS - 1) / FK_WARPS) // 2032
#define HEAD_BASE   PROJ_BLOCKS
#define CL_BASE     (PROJ_BLOCKS + HEAD_BLOCKS)
#define NBLOCKS     (PROJ_BLOCKS + HEAD_BLOCKS + CL_BLOCKS)

// Scratch (allocation-free __device__ globals; reset by the last block)
__device__ float g_head_logits[NHEAD];
__device__ float g_proj[NPROJ];
__device__ float g_cl[NCL];       // cluster logits, vocab order (t - 10000)
__device__ float g_sumexp[5];
__device__ int   g_proj_ctr;
__device__ int   g_done;

__device__ __forceinline__ float warp_sum(float v) {
#pragma unroll
    for (int o = 16; o; o >>= 1) v += __shfl_xor_sync(0xffffffffu, v, o);
    return v;
}
__device__ __forceinline__ float half16_sum(float v) {   // reduce within 16-lane halves
#pragma unroll
    for (int o = 8; o; o >>= 1) v += __shfl_xor_sync(0xffffffffu, v, o);
    return v;
}
__device__ __forceinline__ float dot4(float4 a, float4 b) {
    return a.x * b.x + a.y * b.y + a.z * b.z + a.w * b.w;
}

// ---------------------------------------------------------------------------
// Single fused kernel. Grid = [proj 60 | head 626 | cluster 2032], 512 thr.
// Proj blocks release g_proj via fence + g_proj_ctr; head blocks stream
// independently (hiding proj); cluster blocks spin briefly then consume via
// __ldcg. EVERY block ends with fence + g_done increment; the last block
// runs the loss epilogue (gathers via __ldcg from L2-resident logits) and
// resets all scratch counters for the next graph replay.
// ---------------------------------------------------------------------------
__global__ void __launch_bounds__(FK_THREADS)
fused_kernel(const float* __restrict__ feature,
             const int*   __restrict__ targets,
             const float* __restrict__ head_w,
             const float* __restrict__ t0p, const float* __restrict__ t0w,
             const float* __restrict__ t1p, const float* __restrict__ t1w,
             const float* __restrict__ t2p, const float* __restrict__ t2w,
             const float* __restrict__ t3p, const float* __restrict__ t3w,
             float* __restrict__ out) {
    __shared__ float sv[D];
    __shared__ float s_sum;
    __shared__ int   s_last;
    const int tid = threadIdx.x, lane = tid & 31, warp = tid >> 5;
    const int bid = blockIdx.x;

    if (tid == 0) s_sum = 0.f;

    if (bid < PROJ_BLOCKS) {
        // ---------------- proj blocks ----------------
        const int row = bid * FK_WARPS + warp;    // 0..959
        const float* w;
        if      (row < 512) w = t0p + (size_t)row * D;
        else if (row < 768) w = t1p + (size_t)(row - 512) * D;
        else if (row < 896) w = t2p + (size_t)(row - 768) * D;
        else                w = t3p + (size_t)(row - 896) * D;

        const float4* w4 = (const float4*)w;
        const float4* f4 = (const float4*)feature;
        float acc = 0.f;
#pragma unroll
        for (int j = 0; j < 8; j++)
            acc += dot4(w4[lane + j * 32], f4[lane + j * 32]);
        acc = warp_sum(acc);
        if (lane == 0) g_proj[row] = acc;
        __syncthreads();
        if (tid == 0) {
            __threadfence();                      // release g_proj
            atomicAdd(&g_proj_ctr, 1);
        }
    } else if (bid < CL_BASE) {
        // ---------------- head blocks ----------------
        for (int i = tid; i < D; i += FK_THREADS) sv[i] = feature[i];
        __syncthreads();
        int row = (bid - HEAD_BASE) * FK_WARPS + warp;
        if (row < NHEAD) {
            const float4* w4 = (const float4*)(head_w + (size_t)row * D);
            const float4* v4 = (const float4*)sv;
            float acc = 0.f;
#pragma unroll
            for (int j = 0; j < 8; j++)
                acc += dot4(w4[lane + j * 32], v4[lane + j * 32]);
            acc = warp_sum(acc);
            if (lane == 0) {
                g_head_logits[row] = acc;
                atomicAdd(&s_sum, __expf(acc));
            }
        }
        __syncthreads();
        if (tid == 0) atomicAdd(&g_sumexp[0], s_sum);
    } else {
        // ---------------- cluster blocks ----------------
        const int c0 = (bid - CL_BASE) * FK_WARPS;       // global chunk base
        int seg, lenf, proj_off, chunk;                  // chunk = segment-local
        const float* wmat;
        if (c0 < 10000)      { seg = 1; lenf = 512; wmat = t0w; chunk = c0 + warp;         proj_off = 0;   }
        else if (c0 < 20000) { seg = 2; lenf = 256; wmat = t1w; chunk = c0 - 10000 + warp; proj_off = 512; }
        else if (c0 < 30000) { seg = 3; lenf = 128; wmat = t2w; chunk = c0 - 20000 + warp; proj_off = 768; }
        else                 { seg = 4; lenf =  64; wmat = t3w; chunk = c0 - 30000 + warp; proj_off = 896; }

        // wait for proj producers (release via fence+ctr; consume via __ldcg/L2)
        if (tid == 0) {
            while (*(volatile int*)&g_proj_ctr < PROJ_BLOCKS) { }
        }
        __syncthreads();
        for (int i = tid; i < lenf; i += FK_THREADS) sv[i] = __ldcg(&g_proj[proj_off + i]);
        __syncthreads();

        const bool valid = (c0 + warp) < CL_CHUNKS;      // only the last t3 block masks
        if (valid) {
            const float4* w4 = (const float4*)wmat + (size_t)chunk * 128;
            const float4* v4 = (const float4*)sv;
            const int vm = (lenf >> 2) - 1;              // power-of-two mask
            float4 w0 = w4[lane];       float4 w1 = w4[lane + 32];
            float4 w2 = w4[lane + 64];  float4 w3 = w4[lane + 96];
            float a0 = dot4(w0, v4[lane & vm]);
            float a1 = dot4(w1, v4[(lane + 32) & vm]);
            float a2 = dot4(w2, v4[(lane + 64) & vm]);
            float a3 = dot4(w3, v4[(lane + 96) & vm]);

            float es = 0.f;
            if (seg == 1) {                       // 1 row/chunk
                float r = warp_sum(a0 + a1 + a2 + a3);
                if (lane == 0) { g_cl[chunk] = r; es = __expf(r); }
            } else if (seg == 2) {                // 2 rows/chunk
                float r0 = warp_sum(a0 + a1);
                float r1 = warp_sum(a2 + a3);
                if (lane == 0) {
                    *(float2*)&g_cl[10000 + chunk * 2] = make_float2(r0, r1);
                    es = __expf(r0) + __expf(r1);
                }
            } else if (seg == 3) {                // 4 rows/chunk
                float r0 = warp_sum(a0), r1 = warp_sum(a1);
                float r2 = warp_sum(a2), r3 = warp_sum(a3);
                if (lane == 0) {
                    *(float4*)&g_cl[30000 + chunk * 4] = make_float4(r0, r1, r2, r3);
                    es = __expf(r0) + __expf(r1) + __expf(r2) + __expf(r3);
                }
            } else {                              // 8 rows/chunk (16-lane halves)
                float h0 = half16_sum(a0), h1 = half16_sum(a1);
                float h2 = half16_sum(a2), h3 = half16_sum(a3);
                float o0 = __shfl_sync(0xffffffffu, h0, 16);
                float o1 = __shfl_sync(0xffffffffu, h1, 16);
                float o2 = __shfl_sync(0xffffffffu, h2, 16);
                float o3 = __shfl_sync(0xffffffffu, h3, 16);
                if (lane == 0) {
                    float* p = &g_cl[70000 + chunk * 8];
                    *(float4*)p       = make_float4(h0, o0, h1, o1);
                    *(float4*)(p + 4) = make_float4(h2, o2, h3, o3);
                    es = __expf(h0) + __expf(o0) + __expf(h1) + __expf(o1)
                       + __expf(h2) + __expf(o2) + __expf(h3) + __expf(o3);
                }
            }
            if (lane == 0) atomicAdd(&s_sum, es);
        }
        __syncthreads();
        if (tid == 0) atomicAdd(&g_sumexp[seg], s_sum);
    }

    // ---------------- completion + loss epilogue (last block only) ----------
    __syncthreads();
    if (tid == 0) {
        __threadfence();                          // release this block's writes
        int old = atomicAdd(&g_done, 1);
        s_last = (old == NBLOCKS - 1);
    }
    __syncthreads();
    if (!s_last) return;

    __shared__ float s_lse[5];
    __shared__ float sh[FK_WARPS];
    if (tid < 5) s_lse[tid] = logf(__ldcg(&g_sumexp[tid]));
    __syncthreads();
    const float lse_h = s_lse[0];

    float local = 0.f;
    const int4* t4p = (const int4*)targets;
#pragma unroll
    for (int k = 0; k < 2; k++) {                 // 4096 / (512 thr * 4) = 2
        int4 t4 = __ldcg(&t4p[tid + k * FK_THREADS]);
        int ts[4] = {t4.x, t4.y, t4.z, t4.w};
#pragma unroll
        for (int m = 0; m < 4; m++) {
            int t = ts[m];
            float lp;
            if (t < SHORTLIST) {
                lp = __ldcg(&g_head_logits[t]) - lse_h;
            } else {
                int ci;
                if      (t < 20000) ci = 0;
                else if (t < 40000) ci = 1;
                else if (t < 80000) ci = 2;
                else                ci = 3;
                lp = __ldcg(&g_cl[t - SHORTLIST]) - s_lse[1 + ci]
                   + __ldcg(&g_head_logits[SHORTLIST + ci]) - lse_h;
            }
            local += lp;
        }
    }
    local = warp_sum(local);
    if (lane == 0) sh[warp] = local;
    __syncthreads();
    if (warp == 0) {
        float v = (lane < FK_WARPS) ? sh[lane] : 0.f;
        v = warp_sum(v);
        if (lane == 0) out[0] = -v / (float)NTGT;
    }

    // reset scratch for the next graph replay (deterministic)
    __syncthreads();
    if (tid == 0) { g_done = 0; g_proj_ctr = 0; }
    if (tid < 5)  g_sumexp[tid] = 0.f;
}

// ---------------------------------------------------------------------------
extern "C" void kernel_launch(void* const* d_in, const int* in_sizes, int n_in,
                              void* d_out, int out_size) {
    const float* feature = (const float*)d_in[0];
    const int*   targets = (const int*)  d_in[1];
    const float* head_w  = (const float*)d_in[2];
    const float* t0p     = (const float*)d_in[3];
    const float* t0w     = (const float*)d_in[4];
    const float* t1p     = (const float*)d_in[5];
    const float* t1w     = (const float*)d_in[6];
    const float* t2p     = (const float*)d_in[7];
    const float* t2w     = (const float*)d_in[8];
    const float* t3p     = (const float*)d_in[9];
    const float* t3w     = (const float*)d_in[10];

    fused_kernel<<<NBLOCKS, FK_THREADS>>>(feature, targets, head_w,
                                          t0p, t0w, t1p, t1w,
                                          t2p, t2w, t3p, t3w,
                                          (float*)d_out);
}

// round 9
// speedup vs baseline: 1.0645x; 1.0645x over previous
#include <cuda_runtime.h>

#define D          1024
#define NHEAD      10004
#define SHORTLIST  10000
#define NPROJ      960
#define NCL        90000
#define NTGT       4096

#define FK_THREADS 512
#define FK_WARPS   16
#define PROJ_BLOCKS 60                                     // 960 rows / 16 warps
#define HEAD_BLOCKS ((NHEAD + FK_WARPS - 1) / FK_WARPS)    // 626
#define CL_CHUNKS   32500    // 10000 + 10000 + 10000 + 2500 (2KB chunks)
#define CL_BLOCKS   ((CL_CHUNKS + FK_WARPS - 1) / FK_WARPS) // 2032
#define HEAD_BASE   PROJ_BLOCKS
#define CL_BASE     (PROJ_BLOCKS + HEAD_BLOCKS)
#define NWORK       (PROJ_BLOCKS + HEAD_BLOCKS + CL_BLOCKS) // 2718 worker blocks
#define NBLOCKS     (NWORK + 1)                             // + dedicated loss block

// Scratch (allocation-free __device__ globals; reset by the loss block)
__device__ float g_head_logits[NHEAD];
__device__ float g_proj[NPROJ];
__device__ float g_cl[NCL];       // cluster logits, vocab order (t - 10000)
__device__ float g_sumexp[5];
__device__ int   g_proj_ctr;
__device__ int   g_done;

__device__ __forceinline__ float warp_sum(float v) {
#pragma unroll
    for (int o = 16; o; o >>= 1) v += __shfl_xor_sync(0xffffffffu, v, o);
    return v;
}
__device__ __forceinline__ float half16_sum(float v) {   // reduce within 16-lane halves
#pragma unroll
    for (int o = 8; o; o >>= 1) v += __shfl_xor_sync(0xffffffffu, v, o);
    return v;
}
__device__ __forceinline__ float dot4(float4 a, float4 b) {
    return a.x * b.x + a.y * b.y + a.z * b.z + a.w * b.w;
}

// Fire-and-forget completion: release fence + RED (return unused, no stall).
__device__ __forceinline__ void signal_done() {
    __threadfence();
    atomicAdd(&g_done, 1);      // return value ignored -> RED
}

// ---------------------------------------------------------------------------
// Single launch. Grid = [proj 60 | head 626 | cluster 2032 | loss 1], 512 thr.
// Workers signal completion fire-and-forget and retire immediately; the loss
// block (last bid -> final wave) spins on the counter, gathers targets from
// L2-resident logits via __ldcg, writes the scalar, and resets scratch.
// ---------------------------------------------------------------------------
__global__ void __launch_bounds__(FK_THREADS)
fused_kernel(const float* __restrict__ feature,
             const int*   __restrict__ targets,
             const float* __restrict__ head_w,
             const float* __restrict__ t0p, const float* __restrict__ t0w,
             const float* __restrict__ t1p, const float* __restrict__ t1w,
             const float* __restrict__ t2p, const float* __restrict__ t2w,
             const float* __restrict__ t3p, const float* __restrict__ t3w,
             float* __restrict__ out) {
    __shared__ float sv[D];
    __shared__ float s_sum;
    const int tid = threadIdx.x, lane = tid & 31, warp = tid >> 5;
    const int bid = blockIdx.x;

    if (tid == 0) s_sum = 0.f;

    if (bid < PROJ_BLOCKS) {
        // ---------------- proj blocks ----------------
        const int row = bid * FK_WARPS + warp;    // 0..959
        const float* w;
        if      (row < 512) w = t0p + (size_t)row * D;
        else if (row < 768) w = t1p + (size_t)(row - 512) * D;
        else if (row < 896) w = t2p + (size_t)(row - 768) * D;
        else                w = t3p + (size_t)(row - 896) * D;

        const float4* w4 = (const float4*)w;
        const float4* f4 = (const float4*)feature;
        float acc = 0.f;
#pragma unroll
        for (int j = 0; j < 8; j++)
            acc += dot4(w4[lane + j * 32], f4[lane + j * 32]);
        acc = warp_sum(acc);
        if (lane == 0) g_proj[row] = acc;
        __syncthreads();
        if (tid == 0) {
            __threadfence();                      // release g_proj
            atomicAdd(&g_proj_ctr, 1);            // RED (return unused)
            atomicAdd(&g_done, 1);                // RED
        }
        return;
    }

    if (bid < CL_BASE) {
        // ---------------- head blocks ----------------
        for (int i = tid; i < D; i += FK_THREADS) sv[i] = feature[i];
        __syncthreads();
        int row = (bid - HEAD_BASE) * FK_WARPS + warp;
        if (row < NHEAD) {
            const float4* w4 = (const float4*)(head_w + (size_t)row * D);
            const float4* v4 = (const float4*)sv;
            float acc = 0.f;
#pragma unroll
            for (int j = 0; j < 8; j++)
                acc += dot4(w4[lane + j * 32], v4[lane + j * 32]);
            acc = warp_sum(acc);
            if (lane == 0) {
                g_head_logits[row] = acc;
                atomicAdd(&s_sum, __expf(acc));
            }
        }
        __syncthreads();
        if (tid == 0) {
            atomicAdd(&g_sumexp[0], s_sum);       // RED
            signal_done();
        }
        return;
    }

    if (bid < NWORK) {
        // ---------------- cluster blocks ----------------
        const int c0 = (bid - CL_BASE) * FK_WARPS;       // global chunk base
        int seg, lenf, proj_off, chunk;                  // chunk = segment-local
        const float* wmat;
        if (c0 < 10000)      { seg = 1; lenf = 512; wmat = t0w; chunk = c0 + warp;         proj_off = 0;   }
        else if (c0 < 20000) { seg = 2; lenf = 256; wmat = t1w; chunk = c0 - 10000 + warp; proj_off = 512; }
        else if (c0 < 30000) { seg = 3; lenf = 128; wmat = t2w; chunk = c0 - 20000 + warp; proj_off = 768; }
        else                 { seg = 4; lenf =  64; wmat = t3w; chunk = c0 - 30000 + warp; proj_off = 896; }

        // wait for proj producers (release via fence+ctr; consume via __ldcg/L2)
        if (tid == 0) {
            while (*(volatile int*)&g_proj_ctr < PROJ_BLOCKS) { }
        }
        __syncthreads();
        for (int i = tid; i < lenf; i += FK_THREADS) sv[i] = __ldcg(&g_proj[proj_off + i]);
        __syncthreads();

        const bool valid = (c0 + warp) < CL_CHUNKS;      // only the last t3 block masks
        if (valid) {
            const float4* w4 = (const float4*)wmat + (size_t)chunk * 128;
            const float4* v4 = (const float4*)sv;
            const int vm = (lenf >> 2) - 1;              // power-of-two mask
            float4 w0 = w4[lane];       float4 w1 = w4[lane + 32];
            float4 w2 = w4[lane + 64];  float4 w3 = w4[lane + 96];
            float a0 = dot4(w0, v4[lane & vm]);
            float a1 = dot4(w1, v4[(lane + 32) & vm]);
            float a2 = dot4(w2, v4[(lane + 64) & vm]);
            float a3 = dot4(w3, v4[(lane + 96) & vm]);

            float es = 0.f;
            if (seg == 1) {                       // 1 row/chunk
                float r = warp_sum(a0 + a1 + a2 + a3);
                if (lane == 0) { g_cl[chunk] = r; es = __expf(r); }
            } else if (seg == 2) {                // 2 rows/chunk
                float r0 = warp_sum(a0 + a1);
                float r1 = warp_sum(a2 + a3);
                if (lane == 0) {
                    *(float2*)&g_cl[10000 + chunk * 2] = make_float2(r0, r1);
                    es = __expf(r0) + __expf(r1);
                }
            } else if (seg == 3) {                // 4 rows/chunk
                float r0 = warp_sum(a0), r1 = warp_sum(a1);
                float r2 = warp_sum(a2), r3 = warp_sum(a3);
                if (lane == 0) {
                    *(float4*)&g_cl[30000 + chunk * 4] = make_float4(r0, r1, r2, r3);
                    es = __expf(r0) + __expf(r1) + __expf(r2) + __expf(r3);
                }
            } else {                              // 8 rows/chunk (16-lane halves)
                float h0 = half16_sum(a0), h1 = half16_sum(a1);
                float h2 = half16_sum(a2), h3 = half16_sum(a3);
                float o0 = __shfl_sync(0xffffffffu, h0, 16);
                float o1 = __shfl_sync(0xffffffffu, h1, 16);
                float o2 = __shfl_sync(0xffffffffu, h2, 16);
                float o3 = __shfl_sync(0xffffffffu, h3, 16);
                if (lane == 0) {
                    float* p = &g_cl[70000 + chunk * 8];
                    *(float4*)p       = make_float4(h0, o0, h1, o1);
                    *(float4*)(p + 4) = make_float4(h2, o2, h3, o3);
                    es = __expf(h0) + __expf(o0) + __expf(h1) + __expf(o1)
                       + __expf(h2) + __expf(o2) + __expf(h3) + __expf(o3);
                }
            }
            if (lane == 0) atomicAdd(&s_sum, es);
        }
        __syncthreads();
        if (tid == 0) {
            atomicAdd(&g_sumexp[seg], s_sum);     // RED
            signal_done();
        }
        return;
    }

    // ---------------- loss block (last bid, final wave) ----------------
    if (tid == 0) {
        while (*(volatile int*)&g_done < NWORK) { }
    }
    __syncthreads();

    __shared__ float s_lse[5];
    __shared__ float sh[FK_WARPS];
    if (tid < 5) s_lse[tid] = logf(__ldcg(&g_sumexp[tid]));
    __syncthreads();
    const float lse_h = s_lse[0];

    float local = 0.f;
    const int4* t4p = (const int4*)targets;
#pragma unroll
    for (int k = 0; k < 2; k++) {                 // 4096 / (512 thr * 4) = 2
        int4 t4 = t4p[tid + k * FK_THREADS];
        int ts[4] = {t4.x, t4.y, t4.z, t4.w};
#pragma unroll
        for (int m = 0; m < 4; m++) {
            int t = ts[m];
            float lp;
            if (t < SHORTLIST) {
                lp = __ldcg(&g_head_logits[t]) - lse_h;
            } else {
                int ci;
                if      (t < 20000) ci = 0;
                else if (t < 40000) ci = 1;
                else if (t < 80000) ci = 2;
                else                ci = 3;
                lp = __ldcg(&g_cl[t - SHORTLIST]) - s_lse[1 + ci]
                   + __ldcg(&g_head_logits[SHORTLIST + ci]) - lse_h;
            }
            local += lp;
        }
    }
    local = warp_sum(local);
    if (lane == 0) sh[warp] = local;
    __syncthreads();
    if (warp == 0) {
        float v = (lane < FK_WARPS) ? sh[lane] : 0.f;
        v = warp_sum(v);
        if (lane == 0) out[0] = -v / (float)NTGT;
    }

    // reset scratch for the next graph replay (deterministic)
    __syncthreads();
    if (tid == 0) { g_done = 0; g_proj_ctr = 0; }
    if (tid < 5)  g_sumexp[tid] = 0.f;
}

// ---------------------------------------------------------------------------
extern "C" void kernel_launch(void* const* d_in, const int* in_sizes, int n_in,
                              void* d_out, int out_size) {
    const float* feature = (const float*)d_in[0];
    const int*   targets = (const int*)  d_in[1];
    const float* head_w  = (const float*)d_in[2];
    const float* t0p     = (const float*)d_in[3];
    const float* t0w     = (const float*)d_in[4];
    const float* t1p     = (const float*)d_in[5];
    const float* t1w     = (const float*)d_in[6];
    const float* t2p     = (const float*)d_in[7];
    const float* t2w     = (const float*)d_in[8];
    const float* t3p     = (const float*)d_in[9];
    const float* t3w     = (const float*)d_in[10];

    fused_kernel<<<NBLOCKS, FK_THREADS>>>(feature, targets, head_w,
                                          t0p, t0w, t1p, t1w,
                                          t2p, t2w, t3p, t3w,
                                          (float*)d_out);
}

// round 10
// speedup vs baseline: 1.0745x; 1.0093x over previous
#include <cuda_runtime.h>

#define D          1024
#define NHEAD      10004
#define SHORTLIST  10000
#define NPROJ      960
#define NCL        90000
#define NTGT       4096

#define FK_THREADS 512
#define FK_WARPS   16
#define PROJ_BLOCKS 60                                     // 960 rows / 16 warps
#define HEAD_BLOCKS ((NHEAD + FK_WARPS - 1) / FK_WARPS)    // 626
// 4KB chunks: t0 5000 (2 rows ea), t1 5000 (4), t2 5000 (8), t3 1250 (16)
#define S1_BLOCKS 313
#define S2_BLOCKS 313
#define S3_BLOCKS 313
#define S4_BLOCKS 79
#define CL_BLOCKS (S1_BLOCKS + S2_BLOCKS + S3_BLOCKS + S4_BLOCKS)  // 1018
#define HEAD_BASE   PROJ_BLOCKS
#define CL_BASE     (PROJ_BLOCKS + HEAD_BLOCKS)
#define NBLOCKS     (PROJ_BLOCKS + HEAD_BLOCKS + CL_BLOCKS)

#define LOSS_BLOCKS 32
#define LOSS_THREADS 128

// Scratch (allocation-free __device__ globals; reset by last loss block)
__device__ float g_head_logits[NHEAD];
__device__ float g_proj[NPROJ];
__device__ float g_cl[NCL];       // cluster logits, vocab order (t - 10000)
__device__ float g_sumexp[5];
__device__ int   g_proj_ctr;
__device__ int   g_loss_done;

__device__ __forceinline__ float warp_sum(float v) {
#pragma unroll
    for (int o = 16; o; o >>= 1) v += __shfl_xor_sync(0xffffffffu, v, o);
    return v;
}
__device__ __forceinline__ float half16_sum(float v) {   // reduce within 16-lane halves
#pragma unroll
    for (int o = 8; o; o >>= 1) v += __shfl_xor_sync(0xffffffffu, v, o);
    return v;
}
__device__ __forceinline__ float dot4(float4 a, float4 b) {
    return a.x * b.x + a.y * b.y + a.z * b.z + a.w * b.w;
}

// ---------------------------------------------------------------------------
// Fused kernel. Grid = [proj 60 | head 626 | cluster 1018], 512 thr, 2 CTA/SM.
// Cluster warps process 4KB chunks with 8 LDG.128 in flight (MLP=8).
// ---------------------------------------------------------------------------
__global__ void __launch_bounds__(FK_THREADS, 2)
fused_kernel(const float* __restrict__ feature,
             const float* __restrict__ head_w,
             const float* __restrict__ t0p, const float* __restrict__ t0w,
             const float* __restrict__ t1p, const float* __restrict__ t1w,
             const float* __restrict__ t2p, const float* __restrict__ t2w,
             const float* __restrict__ t3p, const float* __restrict__ t3w,
             float* __restrict__ out) {
    __shared__ float sv[D];
    __shared__ float s_sum;
    const int tid = threadIdx.x, lane = tid & 31, warp = tid >> 5;
    const int bid = blockIdx.x;

    if (tid == 0) s_sum = 0.f;

    if (bid < PROJ_BLOCKS) {
        // ---------------- proj blocks ----------------
        if (bid == 0 && tid == 0) out[0] = 0.f;
        const int row = bid * FK_WARPS + warp;    // 0..959
        const float* w;
        if      (row < 512) w = t0p + (size_t)row * D;
        else if (row < 768) w = t1p + (size_t)(row - 512) * D;
        else if (row < 896) w = t2p + (size_t)(row - 768) * D;
        else                w = t3p + (size_t)(row - 896) * D;

        const float4* w4 = (const float4*)w;
        const float4* f4 = (const float4*)feature;
        float acc = 0.f;
#pragma unroll
        for (int j = 0; j < 8; j++)
            acc += dot4(w4[lane + j * 32], f4[lane + j * 32]);
        acc = warp_sum(acc);
        if (lane == 0) g_proj[row] = acc;
        __syncthreads();
        if (tid == 0) {
            __threadfence();                      // release g_proj
            atomicAdd(&g_proj_ctr, 1);            // RED (return unused)
        }
        return;
    }

    if (bid < CL_BASE) {
        // ---------------- head blocks ----------------
        for (int i = tid; i < D; i += FK_THREADS) sv[i] = feature[i];
        __syncthreads();
        int row = (bid - HEAD_BASE) * FK_WARPS + warp;
        if (row < NHEAD) {
            const float4* w4 = (const float4*)(head_w + (size_t)row * D);
            const float4* v4 = (const float4*)sv;
            float acc = 0.f;
#pragma unroll
            for (int j = 0; j < 8; j++)
                acc += dot4(w4[lane + j * 32], v4[lane + j * 32]);
            acc = warp_sum(acc);
            if (lane == 0) {
                g_head_logits[row] = acc;
                atomicAdd(&s_sum, __expf(acc));
            }
        }
        __syncthreads();
        if (tid == 0) atomicAdd(&g_sumexp[0], s_sum);
        return;
    }

    // ---------------- cluster blocks: 4KB chunk per warp ----------------
    const int local = bid - CL_BASE;
    int seg, lenf, proj_off, segchunks, chunk;
    const float* wmat;
    if (local < S1_BLOCKS) {
        seg = 1; lenf = 512; wmat = t0w; proj_off = 0;   segchunks = 5000;
        chunk = local * FK_WARPS + warp;
    } else if (local < S1_BLOCKS + S2_BLOCKS) {
        seg = 2; lenf = 256; wmat = t1w; proj_off = 512; segchunks = 5000;
        chunk = (local - S1_BLOCKS) * FK_WARPS + warp;
    } else if (local < S1_BLOCKS + S2_BLOCKS + S3_BLOCKS) {
        seg = 3; lenf = 128; wmat = t2w; proj_off = 768; segchunks = 5000;
        chunk = (local - S1_BLOCKS - S2_BLOCKS) * FK_WARPS + warp;
    } else {
        seg = 4; lenf =  64; wmat = t3w; proj_off = 896; segchunks = 1250;
        chunk = (local - S1_BLOCKS - S2_BLOCKS - S3_BLOCKS) * FK_WARPS + warp;
    }

    // wait for proj producers (release via fence+ctr; consume via __ldcg/L2)
    if (tid == 0) {
        while (*(volatile int*)&g_proj_ctr < PROJ_BLOCKS) { }
    }
    __syncthreads();
    for (int i = tid; i < lenf; i += FK_THREADS) sv[i] = __ldcg(&g_proj[proj_off + i]);
    __syncthreads();

    if (chunk < segchunks) {
        const float4* w4 = (const float4*)wmat + (size_t)chunk * 256;  // 4KB
        const float4* v4 = (const float4*)sv;
        const int vm = (lenf >> 2) - 1;              // power-of-two mask

        // 8 independent LDG.128 in flight (MLP=8), then dot
        float4 wv[8];
#pragma unroll
        for (int k = 0; k < 8; k++) wv[k] = w4[lane + 32 * k];
        float a[8];
#pragma unroll
        for (int k = 0; k < 8; k++) a[k] = dot4(wv[k], v4[(lane + 32 * k) & vm]);

        float es = 0.f;
        if (seg == 1) {                       // 2 rows/chunk (512 f/row)
            float r0 = warp_sum(a[0] + a[1] + a[2] + a[3]);
            float r1 = warp_sum(a[4] + a[5] + a[6] + a[7]);
            if (lane == 0) {
                *(float2*)&g_cl[chunk * 2] = make_float2(r0, r1);
                es = __expf(r0) + __expf(r1);
            }
        } else if (seg == 2) {                // 4 rows/chunk (256 f/row)
            float r0 = warp_sum(a[0] + a[1]);
            float r1 = warp_sum(a[2] + a[3]);
            float r2 = warp_sum(a[4] + a[5]);
            float r3 = warp_sum(a[6] + a[7]);
            if (lane == 0) {
                *(float4*)&g_cl[10000 + chunk * 4] = make_float4(r0, r1, r2, r3);
                es = __expf(r0) + __expf(r1) + __expf(r2) + __expf(r3);
            }
        } else if (seg == 3) {                // 8 rows/chunk (128 f/row)
            float r[8];
#pragma unroll
            for (int k = 0; k < 8; k++) r[k] = warp_sum(a[k]);
            if (lane == 0) {
                float* p = &g_cl[30000 + chunk * 8];
                *(float4*)p       = make_float4(r[0], r[1], r[2], r[3]);
                *(float4*)(p + 4) = make_float4(r[4], r[5], r[6], r[7]);
#pragma unroll
                for (int k = 0; k < 8; k++) es += __expf(r[k]);
            }
        } else {                              // 16 rows/chunk (64 f/row)
            float h[8], o[8];
#pragma unroll
            for (int k = 0; k < 8; k++) {
                h[k] = half16_sum(a[k]);                    // lane0: row 2k
                o[k] = __shfl_sync(0xffffffffu, h[k], 16);  // row 2k+1
            }
            if (lane == 0) {
                float* p = &g_cl[70000 + chunk * 16];
                *(float4*)p        = make_float4(h[0], o[0], h[1], o[1]);
                *(float4*)(p + 4)  = make_float4(h[2], o[2], h[3], o[3]);
                *(float4*)(p + 8)  = make_float4(h[4], o[4], h[5], o[5]);
                *(float4*)(p + 12) = make_float4(h[6], o[6], h[7], o[7]);
#pragma unroll
                for (int k = 0; k < 8; k++) es += __expf(h[k]) + __expf(o[k]);
            }
        }
        if (lane == 0) atomicAdd(&s_sum, es);
    }
    __syncthreads();
    if (tid == 0) atomicAdd(&g_sumexp[seg], s_sum);
}

// ---------------------------------------------------------------------------
// K2: parallel gather-loss. 32 blocks x 128 threads = one target per thread.
// Partials accumulate into out[0] (zeroed by fused_kernel). Last block resets
// scratch for the next graph replay.
// ---------------------------------------------------------------------------
__global__ void __launch_bounds__(LOSS_THREADS)
loss_kernel(const int* __restrict__ targets, float* __restrict__ out) {
    __shared__ float s_lse[5];
    __shared__ float sh[4];
    const int tid = threadIdx.x, lane = tid & 31, warp = tid >> 5;

    if (tid < 5) s_lse[tid] = logf(g_sumexp[tid]);
    __syncthreads();
    const float lse_h = s_lse[0];

    const int t = targets[blockIdx.x * LOSS_THREADS + tid];
    float lp;
    if (t < SHORTLIST) {
        lp = g_head_logits[t] - lse_h;
    } else {
        int ci;
        if      (t < 20000) ci = 0;
        else if (t < 40000) ci = 1;
        else if (t < 80000) ci = 2;
        else                ci = 3;
        lp = g_cl[t - SHORTLIST] - s_lse[1 + ci]
           + g_head_logits[SHORTLIST + ci] - lse_h;
    }

    float local = warp_sum(lp);
    if (lane == 0) sh[warp] = local;
    __syncthreads();
    if (tid == 0) {
        float v = sh[0] + sh[1] + sh[2] + sh[3];
        atomicAdd(out, -v * (1.0f / NTGT));
        // last block resets scratch (all blocks already consumed g_sumexp)
        int old = atomicAdd(&g_loss_done, 1);
        if (old == LOSS_BLOCKS - 1) {
            g_loss_done = 0;
            g_proj_ctr  = 0;
            g_sumexp[0] = 0.f; g_sumexp[1] = 0.f; g_sumexp[2] = 0.f;
            g_sumexp[3] = 0.f; g_sumexp[4] = 0.f;
        }
    }
}

// ---------------------------------------------------------------------------
extern "C" void kernel_launch(void* const* d_in, const int* in_sizes, int n_in,
                              void* d_out, int out_size) {
    const float* feature = (const float*)d_in[0];
    const int*   targets = (const int*)  d_in[1];
    const float* head_w  = (const float*)d_in[2];
    const float* t0p     = (const float*)d_in[3];
    const float* t0w     = (const float*)d_in[4];
    const float* t1p     = (const float*)d_in[5];
    const float* t1w     = (const float*)d_in[6];
    const float* t2p     = (const float*)d_in[7];
    const float* t2w     = (const float*)d_in[8];
    const float* t3p     = (const float*)d_in[9];
    const float* t3w     = (const float*)d_in[10];

    fused_kernel<<<NBLOCKS, FK_THREADS>>>(feature, head_w,
                                          t0p, t0w, t1p, t1w,
                                          t2p, t2w, t3p, t3w,
                                          (float*)d_out);
    loss_kernel<<<LOSS_BLOCKS, LOSS_THREADS>>>(targets, (float*)d_out);
}

// round 11
// speedup vs baseline: 1.1393x; 1.0603x over previous
#include <cuda_runtime.h>

#define D          1024
#define NHEAD      10004
#define SHORTLIST  10000
#define NPROJ      960
#define NCL        90000
#define NTGT       4096

#define FK_THREADS 512
#define FK_WARPS   16
#define PROJ_BLOCKS 60                                     // 960 rows / 16 warps
#define HEAD_BLOCKS ((NHEAD + FK_WARPS - 1) / FK_WARPS)    // 626
#define CL_CHUNKS   32500    // 10000 + 10000 + 10000 + 2500 (2KB chunks)
#define CL_BLOCKS   ((CL_CHUNKS + FK_WARPS - 1) / FK_WARPS) // 2032
#define HEAD_BASE   PROJ_BLOCKS
#define CL_BASE     (PROJ_BLOCKS + HEAD_BLOCKS)
#define NBLOCKS     (PROJ_BLOCKS + HEAD_BLOCKS + CL_BLOCKS)

#define LOSS_BLOCKS 32
#define LOSS_THREADS 128

// Scratch (allocation-free __device__ globals; reset by last loss block)
__device__ float g_head_logits[NHEAD];
__device__ float g_proj[NPROJ];
__device__ float g_cl[NCL];       // cluster logits, vocab order (t - 10000)
__device__ float g_sumexp[5];
__device__ int   g_proj_ctr;
__device__ int   g_loss_done;

__device__ __forceinline__ float warp_sum(float v) {
#pragma unroll
    for (int o = 16; o; o >>= 1) v += __shfl_xor_sync(0xffffffffu, v, o);
    return v;
}
__device__ __forceinline__ float half16_sum(float v) {   // reduce within 16-lane halves
#pragma unroll
    for (int o = 8; o; o >>= 1) v += __shfl_xor_sync(0xffffffffu, v, o);
    return v;
}
__device__ __forceinline__ float dot4(float4 a, float4 b) {
    return a.x * b.x + a.y * b.y + a.z * b.z + a.w * b.w;
}

// ---------------------------------------------------------------------------
// Fused kernel. Grid = [proj 60 | head 626 | cluster 2032] blocks, 512 thr.
// (R7 structure: best measured body. 2KB chunks / MLP=4 per cluster warp.)
// Block 0 also zeroes out[0] for the loss kernel's atomic accumulation.
// ---------------------------------------------------------------------------
__global__ void __launch_bounds__(FK_THREADS)
fused_kernel(const float* __restrict__ feature,
             const float* __restrict__ head_w,
             const float* __restrict__ t0p, const float* __restrict__ t0w,
             const float* __restrict__ t1p, const float* __restrict__ t1w,
             const float* __restrict__ t2p, const float* __restrict__ t2w,
             const float* __restrict__ t3p, const float* __restrict__ t3w,
             float* __restrict__ out) {
    __shared__ float sv[D];
    __shared__ float s_sum;
    const int tid = threadIdx.x, lane = tid & 31, warp = tid >> 5;
    const int bid = blockIdx.x;

    if (tid == 0) s_sum = 0.f;

    if (bid < PROJ_BLOCKS) {
        // ---------------- proj blocks ----------------
        if (bid == 0 && tid == 0) out[0] = 0.f;
        const int row = bid * FK_WARPS + warp;    // 0..959
        const float* w;
        if      (row < 512) w = t0p + (size_t)row * D;
        else if (row < 768) w = t1p + (size_t)(row - 512) * D;
        else if (row < 896) w = t2p + (size_t)(row - 768) * D;
        else                w = t3p + (size_t)(row - 896) * D;

        const float4* w4 = (const float4*)w;
        const float4* f4 = (const float4*)feature;
        float acc = 0.f;
#pragma unroll
        for (int j = 0; j < 8; j++)
            acc += dot4(w4[lane + j * 32], f4[lane + j * 32]);
        acc = warp_sum(acc);
        if (lane == 0) g_proj[row] = acc;
        __syncthreads();
        if (tid == 0) {
            __threadfence();                      // release g_proj
            atomicAdd(&g_proj_ctr, 1);            // RED (return unused)
        }
        return;
    }

    if (bid < CL_BASE) {
        // ---------------- head blocks ----------------
        for (int i = tid; i < D; i += FK_THREADS) sv[i] = feature[i];
        __syncthreads();
        int row = (bid - HEAD_BASE) * FK_WARPS + warp;
        if (row < NHEAD) {
            const float4* w4 = (const float4*)(head_w + (size_t)row * D);
            const float4* v4 = (const float4*)sv;
            float acc = 0.f;
#pragma unroll
            for (int j = 0; j < 8; j++)
                acc += dot4(w4[lane + j * 32], v4[lane + j * 32]);
            acc = warp_sum(acc);
            if (lane == 0) {
                g_head_logits[row] = acc;
                atomicAdd(&s_sum, __expf(acc));
            }
        }
        __syncthreads();
        if (tid == 0) atomicAdd(&g_sumexp[0], s_sum);
        return;
    }

    // ---------------- cluster blocks (2KB chunk per warp) ----------------
    const int c0 = (bid - CL_BASE) * FK_WARPS;       // global chunk base
    int seg, lenf, proj_off, chunk;                  // chunk = segment-local
    const float* wmat;
    if (c0 < 10000)      { seg = 1; lenf = 512; wmat = t0w; chunk = c0 + warp;         proj_off = 0;   }
    else if (c0 < 20000) { seg = 2; lenf = 256; wmat = t1w; chunk = c0 - 10000 + warp; proj_off = 512; }
    else if (c0 < 30000) { seg = 3; lenf = 128; wmat = t2w; chunk = c0 - 20000 + warp; proj_off = 768; }
    else                 { seg = 4; lenf =  64; wmat = t3w; chunk = c0 - 30000 + warp; proj_off = 896; }

    // wait for proj producers (release via fence+ctr; consume via __ldcg/L2)
    if (tid == 0) {
        while (*(volatile int*)&g_proj_ctr < PROJ_BLOCKS) { }
    }
    __syncthreads();
    for (int i = tid; i < lenf; i += FK_THREADS) sv[i] = __ldcg(&g_proj[proj_off + i]);
    __syncthreads();

    const bool valid = (c0 + warp) < CL_CHUNKS;      // only the last t3 block masks
    if (valid) {
        const float4* w4 = (const float4*)wmat + (size_t)chunk * 128;
        const float4* v4 = (const float4*)sv;
        const int vm = (lenf >> 2) - 1;              // power-of-two mask
        float4 w0 = w4[lane];       float4 w1 = w4[lane + 32];
        float4 w2 = w4[lane + 64];  float4 w3 = w4[lane + 96];
        float a0 = dot4(w0, v4[lane & vm]);
        float a1 = dot4(w1, v4[(lane + 32) & vm]);
        float a2 = dot4(w2, v4[(lane + 64) & vm]);
        float a3 = dot4(w3, v4[(lane + 96) & vm]);

        float es = 0.f;
        if (seg == 1) {                       // 1 row/chunk
            float r = warp_sum(a0 + a1 + a2 + a3);
            if (lane == 0) { g_cl[chunk] = r; es = __expf(r); }
        } else if (seg == 2) {                // 2 rows/chunk
            float r0 = warp_sum(a0 + a1);
            float r1 = warp_sum(a2 + a3);
            if (lane == 0) {
                *(float2*)&g_cl[10000 + chunk * 2] = make_float2(r0, r1);
                es = __expf(r0) + __expf(r1);
            }
        } else if (seg == 3) {                // 4 rows/chunk
            float r0 = warp_sum(a0), r1 = warp_sum(a1);
            float r2 = warp_sum(a2), r3 = warp_sum(a3);
            if (lane == 0) {
                *(float4*)&g_cl[30000 + chunk * 4] = make_float4(r0, r1, r2, r3);
                es = __expf(r0) + __expf(r1) + __expf(r2) + __expf(r3);
            }
        } else {                              // 8 rows/chunk (16-lane halves)
            float h0 = half16_sum(a0), h1 = half16_sum(a1);
            float h2 = half16_sum(a2), h3 = half16_sum(a3);
            float o0 = __shfl_sync(0xffffffffu, h0, 16);
            float o1 = __shfl_sync(0xffffffffu, h1, 16);
            float o2 = __shfl_sync(0xffffffffu, h2, 16);
            float o3 = __shfl_sync(0xffffffffu, h3, 16);
            if (lane == 0) {
                float* p = &g_cl[70000 + chunk * 8];
                *(float4*)p       = make_float4(h0, o0, h1, o1);
                *(float4*)(p + 4) = make_float4(h2, o2, h3, o3);
                es = __expf(h0) + __expf(o0) + __expf(h1) + __expf(o1)
                   + __expf(h2) + __expf(o2) + __expf(h3) + __expf(o3);
            }
        }
        if (lane == 0) atomicAdd(&s_sum, es);
    }
    __syncthreads();
    if (tid == 0) atomicAdd(&g_sumexp[seg], s_sum);
}

// ---------------------------------------------------------------------------
// K2: parallel gather-loss, launched with PDL (programmatic stream
// serialization). Its launch/dispatch overlaps the fused kernel; the grid
// dependency sync (implicit completion trigger -> full memory visibility)
// gates actual execution. Last block resets scratch for the next replay.
// ---------------------------------------------------------------------------
__global__ void __launch_bounds__(LOSS_THREADS)
loss_kernel(const int* __restrict__ targets, float* __restrict__ out) {
    cudaGridDependencySynchronize();   // wait for fused_kernel (PDL)

    __shared__ float s_lse[5];
    __shared__ float sh[4];
    const int tid = threadIdx.x, lane = tid & 31, warp = tid >> 5;

    if (tid < 5) s_lse[tid] = logf(g_sumexp[tid]);
    __syncthreads();
    const float lse_h = s_lse[0];

    const int t = targets[blockIdx.x * LOSS_THREADS + tid];
    float lp;
    if (t < SHORTLIST) {
        lp = g_head_logits[t] - lse_h;
    } else {
        int ci;
        if      (t < 20000) ci = 0;
        else if (t < 40000) ci = 1;
        else if (t < 80000) ci = 2;
        else                ci = 3;
        lp = g_cl[t - SHORTLIST] - s_lse[1 + ci]
           + g_head_logits[SHORTLIST + ci] - lse_h;
    }

    float local = warp_sum(lp);
    if (lane == 0) sh[warp] = local;
    __syncthreads();
    if (tid == 0) {
        float v = sh[0] + sh[1] + sh[2] + sh[3];
        atomicAdd(out, -v * (1.0f / NTGT));
        // last block resets scratch (all blocks already consumed g_sumexp)
        int old = atomicAdd(&g_loss_done, 1);
        if (old == LOSS_BLOCKS - 1) {
            g_loss_done = 0;
            g_proj_ctr  = 0;
            g_sumexp[0] = 0.f; g_sumexp[1] = 0.f; g_sumexp[2] = 0.f;
            g_sumexp[3] = 0.f; g_sumexp[4] = 0.f;
        }
    }
}

// ---------------------------------------------------------------------------
extern "C" void kernel_launch(void* const* d_in, const int* in_sizes, int n_in,
                              void* d_out, int out_size) {
    const float* feature = (const float*)d_in[0];
    const int*   targets = (const int*)  d_in[1];
    const float* head_w  = (const float*)d_in[2];
    const float* t0p     = (const float*)d_in[3];
    const float* t0w     = (const float*)d_in[4];
    const float* t1p     = (const float*)d_in[5];
    const float* t1w     = (const float*)d_in[6];
    const float* t2p     = (const float*)d_in[7];
    const float* t2w     = (const float*)d_in[8];
    const float* t3p     = (const float*)d_in[9];
    const float* t3w     = (const float*)d_in[10];

    fused_kernel<<<NBLOCKS, FK_THREADS>>>(feature, head_w,
                                          t0p, t0w, t1p, t1w,
                                          t2p, t2w, t3p, t3w,
                                          (float*)d_out);

    // PDL launch: overlap loss_kernel's launch latency with fused_kernel.
    cudaLaunchConfig_t cfg = {};
    cfg.gridDim  = dim3(LOSS_BLOCKS, 1, 1);
    cfg.blockDim = dim3(LOSS_THREADS, 1, 1);
    cfg.dynamicSmemBytes = 0;
    cfg.stream = 0;   // legacy default stream (same as <<<>>> above)
    cudaLaunchAttribute attrs[1];
    attrs[0].id = cudaLaunchAttributeProgrammaticStreamSerialization;
    attrs[0].val.programmaticStreamSerializationAllowed = 1;
    cfg.attrs = attrs;
    cfg.numAttrs = 1;
    cudaLaunchKernelEx(&cfg, loss_kernel, targets, (float*)d_out);
}

// round 12
// speedup vs baseline: 1.2267x; 1.0767x over previous
#include <cuda_runtime.h>

#define D          1024
#define NHEAD      10004
#define SHORTLIST  10000
#define NPROJ      960
#define NCL        90000
#define NTGT       4096

#define FK_THREADS 512
#define FK_WARPS   16
#define PROJ_BLOCKS 60                                     // 960 rows / 16 warps
#define HEAD_BLOCKS ((NHEAD + FK_WARPS - 1) / FK_WARPS)    // 626
#define CL_CHUNKS   32500    // 10000 + 10000 + 10000 + 2500 (2KB chunks)
#define CL_BLOCKS   ((CL_CHUNKS + FK_WARPS - 1) / FK_WARPS) // 2032
#define HEAD_BASE   PROJ_BLOCKS
#define CL_BASE     (PROJ_BLOCKS + HEAD_BLOCKS)
#define NBLOCKS     (PROJ_BLOCKS + HEAD_BLOCKS + CL_BLOCKS)

#define LOSS_BLOCKS 32
#define LOSS_THREADS 128

// Scratch (allocation-free __device__ globals; reset by last loss block)
__device__ float g_head_logits[NHEAD];
__device__ float g_proj[NPROJ];
__device__ float g_cl[NCL];       // cluster logits, vocab order (t - 10000)
__device__ float g_sumexp[5];
__device__ int   g_proj_ctr;
__device__ int   g_loss_done;

__device__ __forceinline__ float warp_sum(float v) {
#pragma unroll
    for (int o = 16; o; o >>= 1) v += __shfl_xor_sync(0xffffffffu, v, o);
    return v;
}
__device__ __forceinline__ float half16_sum(float v) {   // reduce within 16-lane halves
#pragma unroll
    for (int o = 8; o; o >>= 1) v += __shfl_xor_sync(0xffffffffu, v, o);
    return v;
}
__device__ __forceinline__ float dot4(float4 a, float4 b) {
    return a.x * b.x + a.y * b.y + a.z * b.z + a.w * b.w;
}
// streaming (evict-first) float4 load for read-once weight data
__device__ __forceinline__ float4 ldcs4(const float4* p) {
    return __ldcs(p);
}

// ---------------------------------------------------------------------------
// Fused kernel. Grid = [proj 60 | head 626 | cluster 2032] blocks, 512 thr.
// Weights stream with .cs (read-once, evict-first) so produced logits stay
// L2-resident for the loss kernel. Block 0 zeroes out[0].
// ---------------------------------------------------------------------------
__global__ void __launch_bounds__(FK_THREADS)
fused_kernel(const float* __restrict__ feature,
             const float* __restrict__ head_w,
             const float* __restrict__ t0p, const float* __restrict__ t0w,
             const float* __restrict__ t1p, const float* __restrict__ t1w,
             const float* __restrict__ t2p, const float* __restrict__ t2w,
             const float* __restrict__ t3p, const float* __restrict__ t3w,
             float* __restrict__ out) {
    __shared__ float sv[D];
    __shared__ float s_sum;
    const int tid = threadIdx.x, lane = tid & 31, warp = tid >> 5;
    const int bid = blockIdx.x;

    if (tid == 0) s_sum = 0.f;

    if (bid < PROJ_BLOCKS) {
        // ---------------- proj blocks ----------------
        if (bid == 0 && tid == 0) out[0] = 0.f;
        const int row = bid * FK_WARPS + warp;    // 0..959
        const float* w;
        if      (row < 512) w = t0p + (size_t)row * D;
        else if (row < 768) w = t1p + (size_t)(row - 512) * D;
        else if (row < 896) w = t2p + (size_t)(row - 768) * D;
        else                w = t3p + (size_t)(row - 896) * D;

        const float4* w4 = (const float4*)w;
        const float4* f4 = (const float4*)feature;
        float acc = 0.f;
#pragma unroll
        for (int j = 0; j < 8; j++)
            acc += dot4(ldcs4(&w4[lane + j * 32]), f4[lane + j * 32]);
        acc = warp_sum(acc);
        if (lane == 0) g_proj[row] = acc;
        __syncthreads();
        if (tid == 0) {
            __threadfence();                      // release g_proj
            atomicAdd(&g_proj_ctr, 1);            // RED (return unused)
        }
        return;
    }

    if (bid < CL_BASE) {
        // ---------------- head blocks ----------------
        for (int i = tid; i < D; i += FK_THREADS) sv[i] = feature[i];
        __syncthreads();
        int row = (bid - HEAD_BASE) * FK_WARPS + warp;
        if (row < NHEAD) {
            const float4* w4 = (const float4*)(head_w + (size_t)row * D);
            const float4* v4 = (const float4*)sv;
            float acc = 0.f;
#pragma unroll
            for (int j = 0; j < 8; j++)
                acc += dot4(ldcs4(&w4[lane + j * 32]), v4[lane + j * 32]);
            acc = warp_sum(acc);
            if (lane == 0) {
                g_head_logits[row] = acc;
                atomicAdd(&s_sum, __expf(acc));
            }
        }
        __syncthreads();
        if (tid == 0) atomicAdd(&g_sumexp[0], s_sum);
        return;
    }

    // ---------------- cluster blocks (2KB chunk per warp, MLP=4) ----------
    const int c0 = (bid - CL_BASE) * FK_WARPS;       // global chunk base
    int seg, lenf, proj_off, chunk;                  // chunk = segment-local
    const float* wmat;
    if (c0 < 10000)      { seg = 1; lenf = 512; wmat = t0w; chunk = c0 + warp;         proj_off = 0;   }
    else if (c0 < 20000) { seg = 2; lenf = 256; wmat = t1w; chunk = c0 - 10000 + warp; proj_off = 512; }
    else if (c0 < 30000) { seg = 3; lenf = 128; wmat = t2w; chunk = c0 - 20000 + warp; proj_off = 768; }
    else                 { seg = 4; lenf =  64; wmat = t3w; chunk = c0 - 30000 + warp; proj_off = 896; }

    // wait for proj producers (release via fence+ctr; consume via __ldcg/L2)
    if (tid == 0) {
        while (*(volatile int*)&g_proj_ctr < PROJ_BLOCKS) { }
    }
    __syncthreads();
    for (int i = tid; i < lenf; i += FK_THREADS) sv[i] = __ldcg(&g_proj[proj_off + i]);
    __syncthreads();

    const bool valid = (c0 + warp) < CL_CHUNKS;      // only the last t3 block masks
    if (valid) {
        const float4* w4 = (const float4*)wmat + (size_t)chunk * 128;
        const float4* v4 = (const float4*)sv;
        const int vm = (lenf >> 2) - 1;              // power-of-two mask
        float4 w0 = ldcs4(&w4[lane]);       float4 w1 = ldcs4(&w4[lane + 32]);
        float4 w2 = ldcs4(&w4[lane + 64]);  float4 w3 = ldcs4(&w4[lane + 96]);
        float a0 = dot4(w0, v4[lane & vm]);
        float a1 = dot4(w1, v4[(lane + 32) & vm]);
        float a2 = dot4(w2, v4[(lane + 64) & vm]);
        float a3 = dot4(w3, v4[(lane + 96) & vm]);

        float es = 0.f;
        if (seg == 1) {                       // 1 row/chunk
            float r = warp_sum(a0 + a1 + a2 + a3);
            if (lane == 0) { g_cl[chunk] = r; es = __expf(r); }
        } else if (seg == 2) {                // 2 rows/chunk
            float r0 = warp_sum(a0 + a1);
            float r1 = warp_sum(a2 + a3);
            if (lane == 0) {
                *(float2*)&g_cl[10000 + chunk * 2] = make_float2(r0, r1);
                es = __expf(r0) + __expf(r1);
            }
        } else if (seg == 3) {                // 4 rows/chunk
            float r0 = warp_sum(a0), r1 = warp_sum(a1);
            float r2 = warp_sum(a2), r3 = warp_sum(a3);
            if (lane == 0) {
                *(float4*)&g_cl[30000 + chunk * 4] = make_float4(r0, r1, r2, r3);
                es = __expf(r0) + __expf(r1) + __expf(r2) + __expf(r3);
            }
        } else {                              // 8 rows/chunk (16-lane halves)
            float h0 = half16_sum(a0), h1 = half16_sum(a1);
            float h2 = half16_sum(a2), h3 = half16_sum(a3);
            float o0 = __shfl_sync(0xffffffffu, h0, 16);
            float o1 = __shfl_sync(0xffffffffu, h1, 16);
            float o2 = __shfl_sync(0xffffffffu, h2, 16);
            float o3 = __shfl_sync(0xffffffffu, h3, 16);
            if (lane == 0) {
                float* p = &g_cl[70000 + chunk * 8];
                *(float4*)p       = make_float4(h0, o0, h1, o1);
                *(float4*)(p + 4) = make_float4(h2, o2, h3, o3);
                es = __expf(h0) + __expf(o0) + __expf(h1) + __expf(o1)
                   + __expf(h2) + __expf(o2) + __expf(h3) + __expf(o3);
            }
        }
        if (lane == 0) atomicAdd(&s_sum, es);
    }
    __syncthreads();
    if (tid == 0) atomicAdd(&g_sumexp[seg], s_sum);
}

// ---------------------------------------------------------------------------
// K2: gather-loss with PDL. Targets are loaded BEFORE the grid sync (input
// buffer is independent of the fused kernel), and after the sync each thread
// issues its logit gather and its own sumexp loads concurrently — one L2
// round instead of three, no smem serialization. Last block resets scratch.
// ---------------------------------------------------------------------------
__global__ void __launch_bounds__(LOSS_THREADS)
loss_kernel(const int* __restrict__ targets, float* __restrict__ out) {
    __shared__ float sh[4];
    const int tid = threadIdx.x, lane = tid & 31, warp = tid >> 5;

    // pre-sync: load target & classify (overlaps fused kernel's drain)
    const int t = targets[blockIdx.x * LOSS_THREADS + tid];
    int ci = -1;
    if (t >= SHORTLIST) {
        if      (t < 20000) ci = 0;
        else if (t < 40000) ci = 1;
        else if (t < 80000) ci = 2;
        else                ci = 3;
    }

    cudaGridDependencySynchronize();   // wait for fused_kernel (PDL)

    // post-sync: all loads independent -> single L2 round-trip
    float lp;
    if (ci < 0) {
        float logit = __ldcg(&g_head_logits[t]);
        float se_h  = __ldcg(&g_sumexp[0]);
        lp = logit - logf(se_h);
    } else {
        float logit = __ldcg(&g_cl[t - SHORTLIST]);
        float gate  = __ldcg(&g_head_logits[SHORTLIST + ci]);
        float se_h  = __ldcg(&g_sumexp[0]);
        float se_c  = __ldcg(&g_sumexp[1 + ci]);
        lp = logit + gate - logf(se_h) - logf(se_c);
    }

    float local = warp_sum(lp);
    if (lane == 0) sh[warp] = local;
    __syncthreads();
    if (tid == 0) {
        float v = sh[0] + sh[1] + sh[2] + sh[3];
        atomicAdd(out, -v * (1.0f / NTGT));
        // last block resets scratch (all blocks already consumed g_sumexp)
        int old = atomicAdd(&g_loss_done, 1);
        if (old == LOSS_BLOCKS - 1) {
            g_loss_done = 0;
            g_proj_ctr  = 0;
            g_sumexp[0] = 0.f; g_sumexp[1] = 0.f; g_sumexp[2] = 0.f;
            g_sumexp[3] = 0.f; g_sumexp[4] = 0.f;
        }
    }
}

// ---------------------------------------------------------------------------
extern "C" void kernel_launch(void* const* d_in, const int* in_sizes, int n_in,
                              void* d_out, int out_size) {
    const float* feature = (const float*)d_in[0];
    const int*   targets = (const int*)  d_in[1];
    const float* head_w  = (const float*)d_in[2];
    const float* t0p     = (const float*)d_in[3];
    const float* t0w     = (const float*)d_in[4];
    const float* t1p     = (const float*)d_in[5];
    const float* t1w     = (const float*)d_in[6];
    const float* t2p     = (const float*)d_in[7];
    const float* t2w     = (const float*)d_in[8];
    const float* t3p     = (const float*)d_in[9];
    const float* t3w     = (const float*)d_in[10];

    fused_kernel<<<NBLOCKS, FK_THREADS>>>(feature, head_w,
                                          t0p, t0w, t1p, t1w,
                                          t2p, t2w, t3p, t3w,
                                          (float*)d_out);

    // PDL launch: overlap loss_kernel's launch + pre-sync work with fused_kernel.
    cudaLaunchConfig_t cfg = {};
    cfg.gridDim  = dim3(LOSS_BLOCKS, 1, 1);
    cfg.blockDim = dim3(LOSS_THREADS, 1, 1);
    cfg.dynamicSmemBytes = 0;
    cfg.stream = 0;   // legacy default stream (same as <<<>>> above)
    cudaLaunchAttribute attrs[1];
    attrs[0].id = cudaLaunchAttributeProgrammaticStreamSerialization;
    attrs[0].val.programmaticStreamSerializationAllowed = 1;
    cfg.attrs = attrs;
    cfg.numAttrs = 1;
    cudaLaunchKernelEx(&cfg, loss_kernel, targets, (float*)d_out);
}

// round 13
// speedup vs baseline: 1.3219x; 1.0776x over previous
#include <cuda_runtime.h>

#define D          1024
#define NHEAD      10004
#define SHORTLIST  10000
#define NPROJ      960
#define NCL        90000
#define NTGT       4096

#define FK_THREADS 512
#define FK_WARPS   16
#define PROJ_BLOCKS 60                                     // 960 rows / 16 warps
#define HEAD_BLOCKS ((NHEAD + FK_WARPS - 1) / FK_WARPS)    // 626
// 2KB chunks, 2 chunks per warp (sequential). Tasks per segment:
//   seg1 5000, seg2 5000, seg3 5000, seg4 1250  (task = 2 chunks)
#define S1_BLOCKS 313     // ceil(5000/16)
#define S2_BLOCKS 313
#define S3_BLOCKS 313
#define S4_BLOCKS 79      // ceil(1250/16)
#define CL_BLOCKS (S1_BLOCKS + S2_BLOCKS + S3_BLOCKS + S4_BLOCKS)  // 1018
#define HEAD_BASE   PROJ_BLOCKS
#define CL_BASE     (PROJ_BLOCKS + HEAD_BLOCKS)
#define NBLOCKS     (PROJ_BLOCKS + HEAD_BLOCKS + CL_BLOCKS)

#define LOSS_BLOCKS 32
#define LOSS_THREADS 128

// Scratch (allocation-free __device__ globals; reset by last loss block)
__device__ float g_head_logits[NHEAD];
__device__ float g_proj[NPROJ];
__device__ float g_cl[NCL];       // cluster logits, vocab order (t - 10000)
__device__ float g_sumexp[5];
__device__ int   g_proj_ctr;
__device__ int   g_loss_done;

__device__ __forceinline__ float warp_sum(float v) {
#pragma unroll
    for (int o = 16; o; o >>= 1) v += __shfl_xor_sync(0xffffffffu, v, o);
    return v;
}
__device__ __forceinline__ float half16_sum(float v) {   // reduce within 16-lane halves
#pragma unroll
    for (int o = 8; o; o >>= 1) v += __shfl_xor_sync(0xffffffffu, v, o);
    return v;
}
__device__ __forceinline__ float dot4(float4 a, float4 b) {
    return a.x * b.x + a.y * b.y + a.z * b.z + a.w * b.w;
}
// streaming (evict-first) float4 load for read-once weight data
__device__ __forceinline__ float4 ldcs4(const float4* p) {
    return __ldcs(p);
}

// ---------------------------------------------------------------------------
// Fused kernel. Grid = [proj 60 | head 626 | cluster 1018] blocks, 512 thr.
// Cluster warps run the proven 2KB/MLP=4 body twice (sequential, unroll 1 —
// registers reused, occupancy preserved). Weights stream with .cs.
// ---------------------------------------------------------------------------
__global__ void __launch_bounds__(FK_THREADS)
fused_kernel(const float* __restrict__ feature,
             const float* __restrict__ head_w,
             const float* __restrict__ t0p, const float* __restrict__ t0w,
             const float* __restrict__ t1p, const float* __restrict__ t1w,
             const float* __restrict__ t2p, const float* __restrict__ t2w,
             const float* __restrict__ t3p, const float* __restrict__ t3w,
             float* __restrict__ out) {
    __shared__ float sv[D];
    __shared__ float s_sum;
    const int tid = threadIdx.x, lane = tid & 31, warp = tid >> 5;
    const int bid = blockIdx.x;

    if (tid == 0) s_sum = 0.f;

    if (bid < PROJ_BLOCKS) {
        // ---------------- proj blocks ----------------
        if (bid == 0 && tid == 0) out[0] = 0.f;
        const int row = bid * FK_WARPS + warp;    // 0..959
        const float* w;
        if      (row < 512) w = t0p + (size_t)row * D;
        else if (row < 768) w = t1p + (size_t)(row - 512) * D;
        else if (row < 896) w = t2p + (size_t)(row - 768) * D;
        else                w = t3p + (size_t)(row - 896) * D;

        const float4* w4 = (const float4*)w;
        const float4* f4 = (const float4*)feature;
        float acc = 0.f;
#pragma unroll
        for (int j = 0; j < 8; j++)
            acc += dot4(ldcs4(&w4[lane + j * 32]), f4[lane + j * 32]);
        acc = warp_sum(acc);
        if (lane == 0) g_proj[row] = acc;
        __syncthreads();
        if (tid == 0) {
            __threadfence();                      // release g_proj
            atomicAdd(&g_proj_ctr, 1);            // RED (return unused)
        }
        return;
    }

    if (bid < CL_BASE) {
        // ---------------- head blocks ----------------
        for (int i = tid; i < D; i += FK_THREADS) sv[i] = feature[i];
        __syncthreads();
        int row = (bid - HEAD_BASE) * FK_WARPS + warp;
        if (row < NHEAD) {
            const float4* w4 = (const float4*)(head_w + (size_t)row * D);
            const float4* v4 = (const float4*)sv;
            float acc = 0.f;
#pragma unroll
            for (int j = 0; j < 8; j++)
                acc += dot4(ldcs4(&w4[lane + j * 32]), v4[lane + j * 32]);
            acc = warp_sum(acc);
            if (lane == 0) {
                g_head_logits[row] = acc;
                atomicAdd(&s_sum, __expf(acc));
            }
        }
        __syncthreads();
        if (tid == 0) atomicAdd(&g_sumexp[0], s_sum);
        return;
    }

    // ------- cluster blocks: 2 sequential 2KB chunks per warp (MLP=4) ------
    const int local = bid - CL_BASE;
    int seg, lenf, proj_off, segtasks, task, outbase;
    const float* wmat;
    if (local < S1_BLOCKS) {
        seg = 1; lenf = 512; wmat = t0w; proj_off = 0;   segtasks = 5000;
        task = local * FK_WARPS + warp;                      outbase = 0;
    } else if (local < S1_BLOCKS + S2_BLOCKS) {
        seg = 2; lenf = 256; wmat = t1w; proj_off = 512; segtasks = 5000;
        task = (local - S1_BLOCKS) * FK_WARPS + warp;        outbase = 10000;
    } else if (local < S1_BLOCKS + S2_BLOCKS + S3_BLOCKS) {
        seg = 3; lenf = 128; wmat = t2w; proj_off = 768; segtasks = 5000;
        task = (local - S1_BLOCKS - S2_BLOCKS) * FK_WARPS + warp;  outbase = 30000;
    } else {
        seg = 4; lenf =  64; wmat = t3w; proj_off = 896; segtasks = 1250;
        task = (local - S1_BLOCKS - S2_BLOCKS - S3_BLOCKS) * FK_WARPS + warp;
        outbase = 70000;
    }

    // wait for proj producers (release via fence+ctr; consume via __ldcg/L2)
    if (tid == 0) {
        while (*(volatile int*)&g_proj_ctr < PROJ_BLOCKS) { }
    }
    __syncthreads();
    for (int i = tid; i < lenf; i += FK_THREADS) sv[i] = __ldcg(&g_proj[proj_off + i]);
    __syncthreads();

    if (task < segtasks) {
        const float4* v4 = (const float4*)sv;
        const int vm = (lenf >> 2) - 1;              // power-of-two mask
        float es = 0.f;
#pragma unroll 1
        for (int cc = 0; cc < 2; cc++) {
            const int chunk = task * 2 + cc;         // segment-local 2KB chunk
            const float4* w4 = (const float4*)wmat + (size_t)chunk * 128;
            float4 w0 = ldcs4(&w4[lane]);       float4 w1 = ldcs4(&w4[lane + 32]);
            float4 w2 = ldcs4(&w4[lane + 64]);  float4 w3 = ldcs4(&w4[lane + 96]);
            float a0 = dot4(w0, v4[lane & vm]);
            float a1 = dot4(w1, v4[(lane + 32) & vm]);
            float a2 = dot4(w2, v4[(lane + 64) & vm]);
            float a3 = dot4(w3, v4[(lane + 96) & vm]);

            if (seg == 1) {                       // 1 row/chunk
                float r = warp_sum(a0 + a1 + a2 + a3);
                if (lane == 0) { g_cl[outbase + chunk] = r; es += __expf(r); }
            } else if (seg == 2) {                // 2 rows/chunk
                float r0 = warp_sum(a0 + a1);
                float r1 = warp_sum(a2 + a3);
                if (lane == 0) {
                    *(float2*)&g_cl[outbase + chunk * 2] = make_float2(r0, r1);
                    es += __expf(r0) + __expf(r1);
                }
            } else if (seg == 3) {                // 4 rows/chunk
                float r0 = warp_sum(a0), r1 = warp_sum(a1);
                float r2 = warp_sum(a2), r3 = warp_sum(a3);
                if (lane == 0) {
                    *(float4*)&g_cl[outbase + chunk * 4] = make_float4(r0, r1, r2, r3);
                    es += __expf(r0) + __expf(r1) + __expf(r2) + __expf(r3);
                }
            } else {                              // 8 rows/chunk (16-lane halves)
                float h0 = half16_sum(a0), h1 = half16_sum(a1);
                float h2 = half16_sum(a2), h3 = half16_sum(a3);
                float o0 = __shfl_sync(0xffffffffu, h0, 16);
                float o1 = __shfl_sync(0xffffffffu, h1, 16);
                float o2 = __shfl_sync(0xffffffffu, h2, 16);
                float o3 = __shfl_sync(0xffffffffu, h3, 16);
                if (lane == 0) {
                    float* p = &g_cl[outbase + chunk * 8];
                    *(float4*)p       = make_float4(h0, o0, h1, o1);
                    *(float4*)(p + 4) = make_float4(h2, o2, h3, o3);
                    es += __expf(h0) + __expf(o0) + __expf(h1) + __expf(o1)
                        + __expf(h2) + __expf(o2) + __expf(h3) + __expf(o3);
                }
            }
        }
        if (lane == 0) atomicAdd(&s_sum, es);
    }
    __syncthreads();
    if (tid == 0) atomicAdd(&g_sumexp[seg], s_sum);
}

// ---------------------------------------------------------------------------
// K2: gather-loss with PDL. Targets loaded pre-sync; post-sync loads are all
// independent (one L2 round). Last block resets scratch for next replay.
// ---------------------------------------------------------------------------
__global__ void __launch_bounds__(LOSS_THREADS)
loss_kernel(const int* __restrict__ targets, float* __restrict__ out) {
    __shared__ float sh[4];
    const int tid = threadIdx.x, lane = tid & 31, warp = tid >> 5;

    // pre-sync: load target & classify (overlaps fused kernel's drain)
    const int t = targets[blockIdx.x * LOSS_THREADS + tid];
    int ci = -1;
    if (t >= SHORTLIST) {
        if      (t < 20000) ci = 0;
        else if (t < 40000) ci = 1;
        else if (t < 80000) ci = 2;
        else                ci = 3;
    }

    cudaGridDependencySynchronize();   // wait for fused_kernel (PDL)

    float lp;
    if (ci < 0) {
        float logit = __ldcg(&g_head_logits[t]);
        float se_h  = __ldcg(&g_sumexp[0]);
        lp = logit - logf(se_h);
    } else {
        float logit = __ldcg(&g_cl[t - SHORTLIST]);
        float gate  = __ldcg(&g_head_logits[SHORTLIST + ci]);
        float se_h  = __ldcg(&g_sumexp[0]);
        float se_c  = __ldcg(&g_sumexp[1 + ci]);
        lp = logit + gate - logf(se_h) - logf(se_c);
    }

    float local = warp_sum(lp);
    if (lane == 0) sh[warp] = local;
    __syncthreads();
    if (tid == 0) {
        float v = sh[0] + sh[1] + sh[2] + sh[3];
        atomicAdd(out, -v * (1.0f / NTGT));
        int old = atomicAdd(&g_loss_done, 1);
        if (old == LOSS_BLOCKS - 1) {
            g_loss_done = 0;
            g_proj_ctr  = 0;
            g_sumexp[0] = 0.f; g_sumexp[1] = 0.f; g_sumexp[2] = 0.f;
            g_sumexp[3] = 0.f; g_sumexp[4] = 0.f;
        }
    }
}

// ---------------------------------------------------------------------------
extern "C" void kernel_launch(void* const* d_in, const int* in_sizes, int n_in,
                              void* d_out, int out_size) {
    const float* feature = (const float*)d_in[0];
    const int*   targets = (const int*)  d_in[1];
    const float* head_w  = (const float*)d_in[2];
    const float* t0p     = (const float*)d_in[3];
    const float* t0w     = (const float*)d_in[4];
    const float* t1p     = (const float*)d_in[5];
    const float* t1w     = (const float*)d_in[6];
    const float* t2p     = (const float*)d_in[7];
    const float* t2w     = (const float*)d_in[8];
    const float* t3p     = (const float*)d_in[9];
    const float* t3w     = (const float*)d_in[10];

    fused_kernel<<<NBLOCKS, FK_THREADS>>>(feature, head_w,
                                          t0p, t0w, t1p, t1w,
                                          t2p, t2w, t3p, t3w,
                                          (float*)d_out);

    // PDL launch: overlap loss_kernel's launch + pre-sync work with fused_kernel.
    cudaLaunchConfig_t cfg = {};
    cfg.gridDim  = dim3(LOSS_BLOCKS, 1, 1);
    cfg.blockDim = dim3(LOSS_THREADS, 1, 1);
    cfg.dynamicSmemBytes = 0;
    cfg.stream = 0;   // legacy default stream (same as <<<>>> above)
    cudaLaunchAttribute attrs[1];
    attrs[0].id = cudaLaunchAttributeProgrammaticStreamSerialization;
    attrs[0].val.programmaticStreamSerializationAllowed = 1;
    cfg.attrs = attrs;
    cfg.numAttrs = 1;
    cudaLaunchKernelEx(&cfg, loss_kernel, targets, (float*)d_out);
}